// round 13
// baseline (speedup 1.0000x reference)
#include <cuda_runtime.h>
#include <cuda_fp16.h>
#include <cstdint>

// ---------------------------------------------------------------------------
// Fused LSTMDiscriminator, round 13: cluster-of-2 split-M.
// 64 clusters x 2 CTAs (grid 128). Cluster owns 8 agents; CTA rank r computes
// all 4 gates for units [64r, 64r+64) -> HALF the HMMA work per CTA.
// h(t+1) written to both CTAs' B tiles via DSMEM; cluster barrier per step.
// Gate exchange between partner threads via one shfl.xor(16) pair.
// Prep kernel + PDL retained from R12.
// ---------------------------------------------------------------------------

#define GATES    512
#define HID      128
#define EMB      64
#define NSEL     512
#define MAXSTEPS 20
#define PW1      129
#define PW2      65
#define NBLK     128
#define NTHR     512

// SMEM layout (bytes)
#define OFF_XS   0                        // 4096 : h ping-pong [2][128 units][8 agents] f16
#define OFF_VMT  4096                     // 2560 : float4 (vx,vy,mask,0) [8 agents][20]
#define OFF_SH   6656                     // 2048 : final h fp32 [4 local agents][128]
#define OFF_S1   8704                     // 1024
#define OFF_S2   9728                     // 512
#define OFF_W1S  10240                    // 33024: W1 pitch-129
#define OFF_W2S  43264                    // 8320 : W2 pitch-65
#define SMEM_TOTAL 51584

// shared precomputed state (written by prep_kernel each call — deterministic)
__device__ __align__(16) uint4  g_Afrag[8 * 1024];        // [kc][rank*512+tid]
__device__ __align__(16) float4 g_wc[GATES];              // folded input coefs
__device__ __align__(16) float4 g_vmt[NSEL * MAXSTEPS];   // (vx,vy,mask,0)

__device__ __forceinline__ float tanha(float x) {
    float y;
    asm("tanh.approx.f32 %0, %1;" : "=f"(y) : "f"(x));
    return y;
}
__device__ __forceinline__ float sigf(float x) {
    return fmaf(tanha(0.5f * x), 0.5f, 0.5f);
}
__device__ __forceinline__ void mma_acc(float d[4], const uint32_t* a,
                                        uint32_t b0, uint32_t b1) {
    asm volatile(
        "mma.sync.aligned.m16n8k16.row.col.f32.f16.f16.f32 "
        "{%0,%1,%2,%3},{%4,%5,%6,%7},{%8,%9},{%0,%1,%2,%3};"
        : "+f"(d[0]), "+f"(d[1]), "+f"(d[2]), "+f"(d[3])
        : "r"(a[0]), "r"(a[1]), "r"(a[2]), "r"(a[3]), "r"(b0), "r"(b1));
}

#define CLUSTER_ARRIVE() asm volatile("barrier.cluster.arrive.aligned;" ::: "memory")
#define CLUSTER_WAIT()   asm volatile("barrier.cluster.wait.aligned;"   ::: "memory")

// =============================== prep kernel ================================
__global__ void __launch_bounds__(512) prep_kernel(
    const float* __restrict__ obs, const float* __restrict__ pred,
    const void*  __restrict__ bsplit,
    const float* __restrict__ W_emb, const float* __restrict__ b_emb,
    const float* __restrict__ W_ih,  const float* __restrict__ W_hh,
    const float* __restrict__ b_ih,  const float* __restrict__ b_hh,
    int N, int T_obs, int steps)
{
    cudaTriggerProgrammaticLaunchCompletion();

    const int b = blockIdx.x, tid = threadIdx.x;

    if (b < 16) {
        // A-fragment packing for the cluster split-M scheme.
        // Per CTA rank r: warp w owns one m16 tile with rows m = gate*4 + du,
        // gates {g, g+2} at unit u = 64r + 4w + du.
        const int i     = b * 512 + tid;
        const int tid_m = i & 511;
        const int rnk   = (i >> 9) & 1;
        const int kc    = i >> 10;                 // 0..7
        const int wm    = tid_m >> 5;              // warp 0..15
        const int lane  = tid_m & 31;
        const int rr    = lane >> 2;
        const int q     = lane & 3;
        const int gA    = rr >> 2;                 // 0 or 1
        const int du    = rr & 3;
        const int u     = 64 * rnk + 4 * wm + du;
        const int k     = kc * 16 + 2 * q;
        const float* WA = W_hh + (size_t)(gA * 128 + u) * HID;        // gate gA
        const float* WB = W_hh + (size_t)((gA + 2) * 128 + u) * HID;  // gate gA+2
        __half2 hx = __floats2half2_rn(WA[k],     WA[k + 1]);
        __half2 hy = __floats2half2_rn(WB[k],     WB[k + 1]);
        __half2 hz = __floats2half2_rn(WA[k + 8], WA[k + 9]);
        __half2 hw = __floats2half2_rn(WB[k + 8], WB[k + 9]);
        uint4 o;
        o.x = *(const uint32_t*)&hx;
        o.y = *(const uint32_t*)&hy;
        o.z = *(const uint32_t*)&hz;
        o.w = *(const uint32_t*)&hw;
        g_Afrag[kc * 1024 + rnk * 512 + tid_m] = o;
    } else if (b == 16) {
        // fold W_ih @ W_emb (+bias) via 16-lane shuffle reduction
        const int e0 = (tid & 15) << 2;
        float we0[4], we1[4], be4[4];
        #pragma unroll
        for (int j = 0; j < 4; j++) {
            float2 we = ((const float2*)W_emb)[e0 + j];
            we0[j] = we.x; we1[j] = we.y;
            be4[j] = b_emb[e0 + j];
        }
        #pragma unroll
        for (int kk = 0; kk < 16; kk++) {
            const int row = (tid >> 4) + 32 * kk;
            float4 v = *(const float4*)(W_ih + (size_t)row * EMB + e0);
            float p0 = v.x*we0[0] + v.y*we0[1] + v.z*we0[2] + v.w*we0[3];
            float p1 = v.x*we1[0] + v.y*we1[1] + v.z*we1[2] + v.w*we1[3];
            float p2 = v.x*be4[0] + v.y*be4[1] + v.z*be4[2] + v.w*be4[3];
            #pragma unroll
            for (int mdist = 8; mdist >= 1; mdist >>= 1) {
                p0 += __shfl_xor_sync(0xffffffffu, p0, mdist);
                p1 += __shfl_xor_sync(0xffffffffu, p1, mdist);
                p2 += __shfl_xor_sync(0xffffffffu, p2, mdist);
            }
            if ((tid & 15) == 0) {
                float bc = p2 + b_ih[row] + b_hh[row];
                g_wc[row] = make_float4(4.0f * p0, 4.0f * p1, bc, 0.f);
            }
        }
    } else {
        // velocity/mask gather for all 512 selected agents
        const int item = (b - 17) * 512 + tid;
        if (item < NSEL * steps) {
            const int row = item / steps;
            const int t   = item - row * steps;
            const int* p32 = (const int*)bsplit;   // dtype-robust int32/int64
            int agent = (p32[NSEL] == N) ? p32[row]
                                         : (int)((const long long*)bsplit)[row];
            const float* f0 = (t < T_obs)
                ? obs  + ((size_t)t * N + agent) * 2
                : pred + ((size_t)(t - T_obs) * N + agent) * 2;
            int t1 = t + 1;
            const float* f1 = (t1 < T_obs)
                ? obs  + ((size_t)t1 * N + agent) * 2
                : pred + ((size_t)(t1 - T_obs) * N + agent) * 2;
            float x0 = f0[0], x1 = f1[0];
            float y0 = f0[1], y1 = f1[1];
            bool m = !(isnan(x0) || isnan(x1));
            g_vmt[row * MAXSTEPS + t] = make_float4(m ? (x1 - x0) : 0.f,
                                                    m ? (y1 - y0) : 0.f,
                                                    m ? 1.f : 0.f, 0.f);
        }
    }
}

// =============================== main kernel ================================
__global__ void __launch_bounds__(NTHR, 1) fused_kernel(
    const float* __restrict__ W1, const float* __restrict__ b1,
    const float* __restrict__ W2, const float* __restrict__ b2,
    const float* __restrict__ W3, const float* __restrict__ b3,
    float* __restrict__ out,
    int steps)
{
    extern __shared__ char smraw[];
    __half*  Xs    = (__half*) (smraw + OFF_XS);   // [2][128][8]
    float4*  s_vmt = (float4*) (smraw + OFF_VMT);  // [agent 0..7][t]
    float*   sh    = (float*)  (smraw + OFF_SH);   // [4 local agents][128]
    float*   s1    = (float*)  (smraw + OFF_S1);
    float*   s2    = (float*)  (smraw + OFF_S2);
    float*   W1s   = (float*)  (smraw + OFF_W1S);
    float*   W2s   = (float*)  (smraw + OFF_W2S);

    const int tid  = threadIdx.x;
    const int w    = tid >> 5;
    const int lane = tid & 31;
    const int rr   = lane >> 2;
    const int q    = lane & 3;
    const int gA   = rr >> 2;            // 0: gates {i,g}; 1: gates {f,o}
    const int du   = rr & 3;

    uint32_t rank;
    asm("mov.u32 %0, %%cluster_ctarank;" : "=r"(rank));
    const int u  = 64 * (int)rank + 4 * w + du;   // unit owned by this thread
    const int am = 2 * q + gA;                    // agent (0..7) owned

    uint32_t smb;
    asm("{ .reg .u64 t; cvta.to.shared.u64 t, %1; cvt.u32.u64 %0, t; }"
        : "=r"(smb) : "l"(smraw));

    // ===== independent prologue (overlaps prep via PDL) ====================
    #pragma unroll
    for (int k = 0; k < 4; k++) {
        int i = tid + 512 * k;
        float4 v = ((const float4*)W1)[i];
        int row = i >> 5;
        int col = (i & 31) << 2;
        float* p = W1s + row * PW1 + col;
        p[0] = v.x; p[1] = v.y; p[2] = v.z; p[3] = v.w;
    }
    {
        int i = tid;
        float4 v = ((const float4*)W2)[i];
        int row = i >> 4;
        int col = (i & 15) << 2;
        float* p = W2s + row * PW2 + col;
        p[0] = v.x; p[1] = v.y; p[2] = v.z; p[3] = v.w;
    }
    ((uint32_t*)Xs)[tid]       = 0u;   // zero both h buffers (4096 B)
    ((uint32_t*)Xs)[tid + 512] = 0u;

    CLUSTER_ARRIVE();   // zeros published; first WAIT in loop pairs with this

    // ===== dependent prologue ==============================================
    cudaGridDependencySynchronize();

    // A fragments (8 coalesced LDG.128 -> 32 regs)
    uint4 Af[8];
    #pragma unroll
    for (int kc = 0; kc < 8; kc++)
        Af[kc] = g_Afrag[kc * 1024 + (int)rank * 512 + tid];

    // folded input coefs for this thread's two gates at unit u
    float4 wcA = g_wc[gA * 128 + u];           // gate gA
    float4 wcC = g_wc[(gA + 2) * 128 + u];     // gate gA+2

    // vmt slice for this cluster's 8 agents (160 float4, coalesced)
    const int cl8 = (blockIdx.x & ~1) * 4;     // first selected row of cluster
    if (tid < 8 * MAXSTEPS)
        s_vmt[tid] = g_vmt[cl8 * MAXSTEPS + tid];

    __syncthreads();   // intra-CTA: vmt/W staging visible

    float c0 = 0.f, h0 = 0.f;                  // cell (u, am)

    const uint32_t xs_base  = smb + OFF_XS;
    const uint32_t ldm_off  = xs_base + lane * 16;
    const uint32_t sts_loc  = xs_base + u * 16 + am * 2;
    uint32_t sts_rem;
    asm("mapa.shared::cluster.u32 %0, %1, %2;"
        : "=r"(sts_rem) : "r"(sts_loc), "r"(rank ^ 1));
    // final fp32 h target (for MLP): CTA (am>>2), local agent (am&3)
    const uint32_t sh_off = smb + OFF_SH + (uint32_t)(((am & 3) * HID + u) * 4);
    uint32_t sh_rem;
    asm("mapa.shared::cluster.u32 %0, %1, %2;"
        : "=r"(sh_rem) : "r"(sh_off), "r"(rank ^ 1));
    const bool h_local = ((uint32_t)(am >> 2) == rank);

    const float4* vmt0 = s_vmt + (2 * q)     * MAXSTEPS;
    const float4* vmt1 = s_vmt + (2 * q + 1) * MAXSTEPS;
    const bool gA0 = (gA == 0);

    // =========================== recurrence ===============================
    #pragma unroll 1
    for (int t = 0; t < steps; t++) {
        const int cur = t & 1;

        // seeds for the 4 (gate, agent) pairs this thread accumulates
        float4 v0 = vmt0[t];
        float4 v1 = vmt1[t];
        float d_a[4], d_b[4];
        d_a[0] = fmaf(v0.x, wcA.x, fmaf(v0.y, wcA.y, wcA.z));
        d_a[1] = fmaf(v1.x, wcA.x, fmaf(v1.y, wcA.y, wcA.z));
        d_a[2] = fmaf(v0.x, wcC.x, fmaf(v0.y, wcC.y, wcC.z));
        d_a[3] = fmaf(v1.x, wcC.x, fmaf(v1.y, wcC.y, wcC.z));
        #pragma unroll
        for (int i = 0; i < 4; i++) d_b[i] = 0.f;
        const float mz = gA0 ? v0.z : v1.z;

        CLUSTER_WAIT();   // h(t) complete in BOTH CTAs' tiles

        const uint32_t xc = ldm_off + cur * 2048;
        #pragma unroll
        for (int cch = 0; cch < 4; cch++) {
            uint32_t b0, b1, b2, b3;
            asm volatile(
                "ldmatrix.sync.aligned.m8n8.x4.trans.shared.b16 "
                "{%0,%1,%2,%3}, [%4];"
                : "=r"(b0), "=r"(b1), "=r"(b2), "=r"(b3)
                : "r"(xc + cch * 512));
            mma_acc(d_a, (const uint32_t*)&Af[2 * cch],     b0, b1);
            mma_acc(d_b, (const uint32_t*)&Af[2 * cch + 1], b2, b3);
        }
        float d0 = d_a[0] + d_b[0];
        float d1 = d_a[1] + d_b[1];
        float d2 = d_a[2] + d_b[2];
        float d3 = d_a[3] + d_b[3];

        // partner exchange (lane ^ 16): each thread assembles all 4 gates of
        // its cell (u, am). gA0 thread keeps agent 2q; partner keeps 2q+1.
        float vs1 = gA0 ? d1 : d0;
        float vs2 = gA0 ? d3 : d2;
        float r1  = __shfl_xor_sync(0xffffffffu, vs1, 16);
        float r2  = __shfl_xor_sync(0xffffffffu, vs2, 16);
        float gi_ = gA0 ? d0 : r1;
        float gf_ = gA0 ? r1 : d1;
        float gg_ = gA0 ? d2 : r2;
        float go_ = gA0 ? r2 : d3;

        float iv = sigf (gi_);
        float fv = sigf (gf_);
        float gv = tanha(gg_);
        float ov = sigf (go_);
        float c2 = fmaf(fv, c0, iv * gv);
        float h2 = ov * tanha(c2);
        if (mz != 0.f) { c0 = c2; h0 = h2; }

        // publish h(t+1) to BOTH CTAs' B tiles (buffer cur^1)
        {
            __half hh = __float2half_rn(h0);
            uint16_t hb = *(const uint16_t*)&hh;
            asm volatile("st.shared.b16 [%0], %1;"
                         :: "r"(sts_loc + ((cur ^ 1) << 11)), "h"(hb));
            asm volatile("st.shared::cluster.b16 [%0], %1;"
                         :: "r"(sts_rem + ((cur ^ 1) << 11)), "h"(hb));
        }
        // on the last step also publish fp32 h for the MLP
        if (t == steps - 1) {
            if (h_local)
                asm volatile("st.shared.b32 [%0], %1;"
                             :: "r"(sh_off), "f"(h0));
            else
                asm volatile("st.shared::cluster.b32 [%0], %1;"
                             :: "r"(sh_rem), "f"(h0));
        }
        CLUSTER_ARRIVE();
    }

    CLUSTER_WAIT();   // final h + fp32 exchange visible

    // =========================== fused MLP tail ===========================
    // this CTA handles local agents la=0..3 = global rows blockIdx.x*4 + la
    // layer 1: (4 x 128) @ W1^T -> relu
    if (tid < 256) {
        const int u1 = tid & 63;
        const int aa = tid >> 6;
        float acc = b1[u1];
        const float* wr = W1s + u1 * PW1;
        const float* hv = sh + aa * HID;
        #pragma unroll
        for (int k = 0; k < HID; k++) acc = fmaf(wr[k], hv[k], acc);
        s1[aa * 64 + u1] = fmaxf(acc, 0.f);
    }
    __syncthreads();

    // layer 2: (4 x 64) @ W2^T -> relu
    if (tid < 128) {
        const int u2 = tid & 31;
        const int aa = tid >> 5;
        float acc = b2[u2];
        const float* wr = W2s + u2 * PW2;
        const float* xv = s1 + aa * 64;
        #pragma unroll
        for (int k = 0; k < 64; k++) acc = fmaf(wr[k], xv[k], acc);
        s2[aa * 32 + u2] = fmaxf(acc, 0.f);
    }
    __syncthreads();

    // layer 3
    if (tid < 4) {
        float acc = b3[0];
        #pragma unroll
        for (int k = 0; k < 32; k++) acc += W3[k] * s2[tid * 32 + k];
        out[blockIdx.x * 4 + tid] = fmaxf(acc, 0.f);
    }
}

// ------------------------------- launcher ----------------------------------
extern "C" void kernel_launch(void* const* d_in, const int* in_sizes, int n_in,
                              void* d_out, int out_size) {
    const float* observed   = (const float*)d_in[0];
    const float* prediction = (const float*)d_in[1];
    const void*  bsplit     = d_in[3];
    const float* W_emb      = (const float*)d_in[4];
    const float* b_emb      = (const float*)d_in[5];
    const float* W_ih       = (const float*)d_in[6];
    const float* W_hh       = (const float*)d_in[7];
    const float* b_ih       = (const float*)d_in[8];
    const float* b_hh       = (const float*)d_in[9];
    const float* W1         = (const float*)d_in[10];
    const float* b1         = (const float*)d_in[11];
    const float* W2         = (const float*)d_in[12];
    const float* b2         = (const float*)d_in[13];
    const float* W3         = (const float*)d_in[14];
    const float* b3         = (const float*)d_in[15];
    float* out = (float*)d_out;

    const int N      = in_sizes[2] / 2;               // goals: (N,2)
    const int T_obs  = in_sizes[0] / (2 * N);
    const int T_pred = in_sizes[1] / (2 * N);
    int steps = T_obs + T_pred - 1;
    if (steps > MAXSTEPS) steps = MAXSTEPS;

    const int vmt_blocks = (NSEL * steps + 511) / 512;
    prep_kernel<<<17 + vmt_blocks, 512>>>(
        observed, prediction, bsplit,
        W_emb, b_emb, W_ih, W_hh, b_ih, b_hh,
        N, T_obs, steps);

    cudaFuncSetAttribute(fused_kernel, cudaFuncAttributeMaxDynamicSharedMemorySize,
                         SMEM_TOTAL);

    cudaLaunchConfig_t cfg = {};
    cfg.gridDim  = dim3(NBLK, 1, 1);
    cfg.blockDim = dim3(NTHR, 1, 1);
    cfg.dynamicSmemBytes = SMEM_TOTAL;
    cfg.stream = 0;
    cudaLaunchAttribute attrs[2];
    attrs[0].id = cudaLaunchAttributeProgrammaticStreamSerialization;
    attrs[0].val.programmaticStreamSerializationAllowed = 1;
    attrs[1].id = cudaLaunchAttributeClusterDimension;
    attrs[1].val.clusterDim.x = 2;
    attrs[1].val.clusterDim.y = 1;
    attrs[1].val.clusterDim.z = 1;
    cfg.attrs = attrs;
    cfg.numAttrs = 2;
    cudaLaunchKernelEx(&cfg, fused_kernel, W1, b1, W2, b2, W3, b3,
                       out, steps);
}

// round 14
// speedup vs baseline: 1.2795x; 1.2795x over previous
#include <cuda_runtime.h>
#include <cuda_fp16.h>
#include <cstdint>

// ---------------------------------------------------------------------------
// Fused LSTMDiscriminator, round 14: R12 (proven 21.0us) + packed f16x2 tanh
// activations. The sigmoid input halving is folded into prep (W rows and wc
// coefficients of gates i,f,o pre-scaled by 0.5), so the epilogue is
// pack -> tanh.approx.f16x2 -> fma. MUFU per thread per step: 5 -> 3.
// Cluster split-M (R13) reverted: cluster barrier+DSMEM cost >> MMA savings.
// ---------------------------------------------------------------------------

#define GATES    512
#define HID      128
#define EMB      64
#define NSEL     512
#define MAXSTEPS 20
#define AG       4
#define PW1      129
#define PW2      65
#define NBLK     (NSEL/AG)   // 128 blocks
#define NTHR     512

// SMEM layout for main kernel (bytes)
#define OFF_XS   0                        // 4096 : h ping-pong [2][128][8] f16
#define OFF_VMT  4096                     // 1280 : float4 (vx,vy,mask,0) [4][20]
#define OFF_SH   5376                     // 2048 : final h fp32 [4][128]
#define OFF_S1   7424                     // 1024
#define OFF_S2   8448                     // 512
#define OFF_W1S  8960                     // 33024: W1 pitch-129
#define OFF_W2S  41984                    // 8320 : W2 pitch-65
#define SMEM_TOTAL 50304

// shared precomputed state (written by prep_kernel each call — deterministic)
__device__ __align__(16) uint4  g_Afrag[16 * 512];        // [j4][tid] frag regs
__device__ __align__(16) float4 g_wc[GATES];              // folded input coefs
__device__ __align__(16) float4 g_vmt[NSEL * MAXSTEPS];   // (vx,vy,mask,0)

__device__ __forceinline__ float tanha(float x) {
    float y;
    asm("tanh.approx.f32 %0, %1;" : "=f"(y) : "f"(x));
    return y;
}

__device__ __forceinline__ void mma_acc(float d[4], const uint32_t* a,
                                        uint32_t b0, uint32_t b1) {
    asm volatile(
        "mma.sync.aligned.m16n8k16.row.col.f32.f16.f16.f32 "
        "{%0,%1,%2,%3},{%4,%5,%6,%7},{%8,%9},{%0,%1,%2,%3};"
        : "+f"(d[0]), "+f"(d[1]), "+f"(d[2]), "+f"(d[3])
        : "r"(a[0]), "r"(a[1]), "r"(a[2]), "r"(a[3]), "r"(b0), "r"(b1));
}

// =============================== prep kernel ================================
__global__ void __launch_bounds__(512) prep_kernel(
    const float* __restrict__ obs, const float* __restrict__ pred,
    const void*  __restrict__ bsplit,
    const float* __restrict__ W_emb, const float* __restrict__ b_emb,
    const float* __restrict__ W_ih,  const float* __restrict__ W_hh,
    const float* __restrict__ b_ih,  const float* __restrict__ b_hh,
    int N, int T_obs, int steps)
{
    // let the dependent fused kernel launch right away (it grid-syncs
    // before consuming our outputs)
    cudaTriggerProgrammaticLaunchCompletion();

    const int b = blockIdx.x, tid = threadIdx.x;

    if (b < 16) {
        // A-fragment packing in exact per-thread register order.
        // tile0 = gates {i(0), g(2)}, tile1 = {f(1), o(3)}; A{tile}[kc] =
        // {gA[k..k+1], gB[k..k+1], gA[k+8..k+9], gB[k+8..k+9]}, k = kc*16+2q
        // Sigmoid-gate rows (i, f, o) pre-scaled by 0.5 (tanh(x/2) identity).
        const int i     = b * 512 + tid;
        const int tid_m = i & 511;
        const int j4    = i >> 9;
        const int u     = 8 * (tid_m >> 5) + ((tid_m >> 2) & 7);
        const int q     = tid_m & 3;
        const int tile  = j4 >> 3;
        const int kc    = j4 & 7;
        const int gA    = tile ? 1 : 0;           // i or f  (sigmoid -> 0.5)
        const int gB    = tile ? 3 : 2;           // o or g  (o -> 0.5, g -> 1)
        const float sB  = tile ? 0.5f : 1.0f;
        const int k     = kc * 16 + 2 * q;
        const float* WA = W_hh + (size_t)(gA * 128 + u) * HID;
        const float* WB = W_hh + (size_t)(gB * 128 + u) * HID;
        __half2 hx = __floats2half2_rn(0.5f * WA[k],     0.5f * WA[k + 1]);
        __half2 hy = __floats2half2_rn(sB   * WB[k],     sB   * WB[k + 1]);
        __half2 hz = __floats2half2_rn(0.5f * WA[k + 8], 0.5f * WA[k + 9]);
        __half2 hw = __floats2half2_rn(sB   * WB[k + 8], sB   * WB[k + 9]);
        uint4 o;
        o.x = *(const uint32_t*)&hx;
        o.y = *(const uint32_t*)&hy;
        o.z = *(const uint32_t*)&hz;
        o.w = *(const uint32_t*)&hw;
        g_Afrag[j4 * 512 + tid_m] = o;
    } else if (b == 16) {
        // fold W_ih @ W_emb (+bias) via 16-lane shuffle reduction.
        // Same 0.5 pre-scale for sigmoid gates (rows with gate != 2).
        const int e0 = (tid & 15) << 2;
        float we0[4], we1[4], be4[4];
        #pragma unroll
        for (int j = 0; j < 4; j++) {
            float2 we = ((const float2*)W_emb)[e0 + j];
            we0[j] = we.x; we1[j] = we.y;
            be4[j] = b_emb[e0 + j];
        }
        #pragma unroll
        for (int kk = 0; kk < 16; kk++) {
            const int row = (tid >> 4) + 32 * kk;
            float4 v = *(const float4*)(W_ih + (size_t)row * EMB + e0);
            float p0 = v.x*we0[0] + v.y*we0[1] + v.z*we0[2] + v.w*we0[3];
            float p1 = v.x*we1[0] + v.y*we1[1] + v.z*we1[2] + v.w*we1[3];
            float p2 = v.x*be4[0] + v.y*be4[1] + v.z*be4[2] + v.w*be4[3];
            #pragma unroll
            for (int mdist = 8; mdist >= 1; mdist >>= 1) {
                p0 += __shfl_xor_sync(0xffffffffu, p0, mdist);
                p1 += __shfl_xor_sync(0xffffffffu, p1, mdist);
                p2 += __shfl_xor_sync(0xffffffffu, p2, mdist);
            }
            if ((tid & 15) == 0) {
                const float sc = ((row >> 7) == 2) ? 1.0f : 0.5f;
                float bc = p2 + b_ih[row] + b_hh[row];
                g_wc[row] = make_float4(4.0f * sc * p0, 4.0f * sc * p1,
                                        sc * bc, 0.f);
            }
        }
    } else {
        // velocity/mask gather for all 512 selected agents
        const int item = (b - 17) * 512 + tid;
        if (item < NSEL * steps) {
            const int row = item / steps;
            const int t   = item - row * steps;
            const int* p32 = (const int*)bsplit;   // dtype-robust int32/int64
            int agent = (p32[NSEL] == N) ? p32[row]
                                         : (int)((const long long*)bsplit)[row];
            const float* f0 = (t < T_obs)
                ? obs  + ((size_t)t * N + agent) * 2
                : pred + ((size_t)(t - T_obs) * N + agent) * 2;
            int t1 = t + 1;
            const float* f1 = (t1 < T_obs)
                ? obs  + ((size_t)t1 * N + agent) * 2
                : pred + ((size_t)(t1 - T_obs) * N + agent) * 2;
            float x0 = f0[0], x1 = f1[0];
            float y0 = f0[1], y1 = f1[1];
            bool m = !(isnan(x0) || isnan(x1));
            g_vmt[row * MAXSTEPS + t] = make_float4(m ? (x1 - x0) : 0.f,
                                                    m ? (y1 - y0) : 0.f,
                                                    m ? 1.f : 0.f, 0.f);
        }
    }
}

// =============================== main kernel ================================
__global__ void __launch_bounds__(NTHR, 1) fused_kernel(
    const float* __restrict__ W1, const float* __restrict__ b1,
    const float* __restrict__ W2, const float* __restrict__ b2,
    const float* __restrict__ W3, const float* __restrict__ b3,
    float* __restrict__ out,
    int steps)
{
    extern __shared__ char smraw[];
    __half*  Xs    = (__half*) (smraw + OFF_XS);   // [2][128][8]
    float4*  s_vmt = (float4*) (smraw + OFF_VMT);  // [agent][t]
    float*   sh    = (float*)  (smraw + OFF_SH);
    float*   s1    = (float*)  (smraw + OFF_S1);
    float*   s2    = (float*)  (smraw + OFF_S2);
    float*   W1s   = (float*)  (smraw + OFF_W1S);
    float*   W2s   = (float*)  (smraw + OFF_W2S);

    const int tid  = threadIdx.x;
    const int w    = tid >> 5;
    const int lane = tid & 31;
    const int r    = lane >> 2;
    const int q    = lane & 3;           // agent owned by this thread
    const int row0 = blockIdx.x * AG;
    const int u    = 8 * w + r;          // hidden unit owned by this thread

    // ===== independent prologue (overlaps prep kernel via PDL) ============
    #pragma unroll
    for (int k = 0; k < 4; k++) {
        int i = tid + 512 * k;
        float4 v = ((const float4*)W1)[i];
        int row = i >> 5;
        int col = (i & 31) << 2;
        float* p = W1s + row * PW1 + col;
        p[0] = v.x; p[1] = v.y; p[2] = v.z; p[3] = v.w;
    }
    {
        int i = tid;
        float4 v = ((const float4*)W2)[i];
        int row = i >> 4;
        int col = (i & 15) << 2;
        float* p = W2s + row * PW2 + col;
        p[0] = v.x; p[1] = v.y; p[2] = v.z; p[3] = v.w;
    }
    ((uint32_t*)Xs)[tid]       = 0u;
    ((uint32_t*)Xs)[tid + 512] = 0u;

    // ===== wait for prep outputs, then dependent prologue ==================
    cudaGridDependencySynchronize();

    // A fragments straight into registers (16 coalesced LDG.128)
    uint4 A0v[8], A1v[8];
    #pragma unroll
    for (int kc = 0; kc < 8; kc++) A0v[kc] = g_Afrag[kc * 512 + tid];
    #pragma unroll
    for (int kc = 0; kc < 8; kc++) A1v[kc] = g_Afrag[(8 + kc) * 512 + tid];

    // folded input coefficients (pre-scaled for sigmoid gates)
    float wc0[4], wc1[4], bcr[4];
    #pragma unroll
    for (int g = 0; g < 4; g++) {
        float4 wc = g_wc[g * 128 + u];
        wc0[g] = wc.x; wc1[g] = wc.y; bcr[g] = wc.z;
    }

    // vmt slice for this block's 4 agents (80 float4, coalesced)
    if (tid < AG * MAXSTEPS)
        s_vmt[tid] = g_vmt[row0 * MAXSTEPS + tid];

    __syncthreads();   // the ONE prologue barrier

    float c0 = 0.f, h0 = 0.f;           // single cell: (agent q, unit u)

    const uint32_t xs_base = (uint32_t)__cvta_generic_to_shared(Xs);
    const uint32_t ldm_off = xs_base + lane * 16;
    const uint32_t sts_off = xs_base + u * 16 + q * 4;
    const float4*  vmt_a   = s_vmt + q * MAXSTEPS;

    // =========================== recurrence ===============================
    #pragma unroll 1
    for (int t = 0; t < steps; t++) {
        const int cur = t & 1;

        float4 vm = vmt_a[t];
        const bool m = (vm.z != 0.f);
        float s_i = fmaf(vm.x, wc0[0], fmaf(vm.y, wc1[0], bcr[0]));
        float s_f = fmaf(vm.x, wc0[1], fmaf(vm.y, wc1[1], bcr[1]));
        float s_g = fmaf(vm.x, wc0[2], fmaf(vm.y, wc1[2], bcr[2]));
        float s_o = fmaf(vm.x, wc0[3], fmaf(vm.y, wc1[3], bcr[3]));

        __syncthreads();   // h(t) stores visible

        // load all 4 B chunks upfront
        uint32_t B[4][4];
        const uint32_t xc = ldm_off + cur * 2048;
        #pragma unroll
        for (int cch = 0; cch < 4; cch++) {
            asm volatile(
                "ldmatrix.sync.aligned.m8n8.x4.trans.shared.b16 "
                "{%0,%1,%2,%3}, [%4];"
                : "=r"(B[cch][0]), "=r"(B[cch][1]),
                  "=r"(B[cch][2]), "=r"(B[cch][3])
                : "r"(xc + cch * 512));
        }

        // tile0: gates i (elem 0, pre-scaled) and g (elem 2) — finish first
        float d0a[4] = { s_i, 0.f, s_g, 0.f };
        float d0b[4] = { 0.f, 0.f, 0.f, 0.f };
        #pragma unroll
        for (int cch = 0; cch < 4; cch++) {
            mma_acc(d0a, (const uint32_t*)&A0v[2 * cch],     B[cch][0], B[cch][1]);
            mma_acc(d0b, (const uint32_t*)&A0v[2 * cch + 1], B[cch][2], B[cch][3]);
        }
        // packed tanh of (i, g) — MUFU overlaps tile1's HMMA below
        uint32_t pk0;
        {
            __half2 hp = __floats2half2_rn(d0a[0] + d0b[0], d0a[2] + d0b[2]);
            asm("tanh.approx.f16x2 %0, %1;"
                : "=r"(pk0) : "r"(*(const uint32_t*)&hp));
        }

        // tile1: gates f (elem 0) and o (elem 2), both pre-scaled
        float d1a[4] = { s_f, 0.f, s_o, 0.f };
        float d1b[4] = { 0.f, 0.f, 0.f, 0.f };
        #pragma unroll
        for (int cch = 0; cch < 4; cch++) {
            mma_acc(d1a, (const uint32_t*)&A1v[2 * cch],     B[cch][0], B[cch][1]);
            mma_acc(d1b, (const uint32_t*)&A1v[2 * cch + 1], B[cch][2], B[cch][3]);
        }
        uint32_t pk1;
        {
            __half2 hp = __floats2half2_rn(d1a[0] + d1b[0], d1a[2] + d1b[2]);
            asm("tanh.approx.f16x2 %0, %1;"
                : "=r"(pk1) : "r"(*(const uint32_t*)&hp));
        }

        __half2 t0 = *(const __half2*)&pk0;   // lo: tanh(i/2), hi: tanh(g)
        __half2 t1 = *(const __half2*)&pk1;   // lo: tanh(f/2), hi: tanh(o/2)
        float iv = fmaf(__low2float(t0),  0.5f, 0.5f);
        float gv = __high2float(t0);
        float fv = fmaf(__low2float(t1),  0.5f, 0.5f);
        float ov = fmaf(__high2float(t1), 0.5f, 0.5f);
        float c2 = fmaf(fv, c0, iv * gv);
        float hv = ov * tanha(c2);
        if (m) { c0 = c2; h0 = hv; }

        {
            __half hh = __float2half_rn(h0);
            asm volatile("st.shared.b16 [%0], %1;"
                         :: "r"(sts_off + ((cur ^ 1) << 11)),
                            "h"(*(const uint16_t*)&hh));
        }
    }

    // =========================== fused MLP tail ===========================
    sh[q * HID + u] = h0;
    __syncthreads();

    // layer 1: (4 x 128) @ W1^T -> relu
    if (tid < 256) {
        const int u1 = tid & 63;
        const int aa = tid >> 6;
        float acc = b1[u1];
        const float* wr = W1s + u1 * PW1;
        const float* hv = sh + aa * HID;
        #pragma unroll
        for (int k = 0; k < HID; k++) acc = fmaf(wr[k], hv[k], acc);
        s1[aa * 64 + u1] = fmaxf(acc, 0.f);
    }
    __syncthreads();

    // layer 2: (4 x 64) @ W2^T -> relu
    if (tid < 128) {
        const int u2 = tid & 31;
        const int aa = tid >> 5;
        float acc = b2[u2];
        const float* wr = W2s + u2 * PW2;
        const float* xv = s1 + aa * 64;
        #pragma unroll
        for (int k = 0; k < 64; k++) acc = fmaf(wr[k], xv[k], acc);
        s2[aa * 32 + u2] = fmaxf(acc, 0.f);
    }
    __syncthreads();

    // layer 3
    if (tid < AG) {
        float acc = b3[0];
        #pragma unroll
        for (int k = 0; k < 32; k++) acc += W3[k] * s2[tid * 32 + k];
        out[row0 + tid] = fmaxf(acc, 0.f);
    }
}

// ------------------------------- launcher ----------------------------------
extern "C" void kernel_launch(void* const* d_in, const int* in_sizes, int n_in,
                              void* d_out, int out_size) {
    const float* observed   = (const float*)d_in[0];
    const float* prediction = (const float*)d_in[1];
    const void*  bsplit     = d_in[3];
    const float* W_emb      = (const float*)d_in[4];
    const float* b_emb      = (const float*)d_in[5];
    const float* W_ih       = (const float*)d_in[6];
    const float* W_hh       = (const float*)d_in[7];
    const float* b_ih       = (const float*)d_in[8];
    const float* b_hh       = (const float*)d_in[9];
    const float* W1         = (const float*)d_in[10];
    const float* b1         = (const float*)d_in[11];
    const float* W2         = (const float*)d_in[12];
    const float* b2         = (const float*)d_in[13];
    const float* W3         = (const float*)d_in[14];
    const float* b3         = (const float*)d_in[15];
    float* out = (float*)d_out;

    const int N      = in_sizes[2] / 2;               // goals: (N,2)
    const int T_obs  = in_sizes[0] / (2 * N);
    const int T_pred = in_sizes[1] / (2 * N);
    int steps = T_obs + T_pred - 1;
    if (steps > MAXSTEPS) steps = MAXSTEPS;

    const int vmt_blocks = (NSEL * steps + 511) / 512;
    prep_kernel<<<17 + vmt_blocks, 512>>>(
        observed, prediction, bsplit,
        W_emb, b_emb, W_ih, W_hh, b_ih, b_hh,
        N, T_obs, steps);

    cudaFuncSetAttribute(fused_kernel, cudaFuncAttributeMaxDynamicSharedMemorySize,
                         SMEM_TOTAL);

    // PDL: fused launches as soon as prep triggers; it grid-syncs internally
    cudaLaunchConfig_t cfg = {};
    cfg.gridDim  = dim3(NBLK, 1, 1);
    cfg.blockDim = dim3(NTHR, 1, 1);
    cfg.dynamicSmemBytes = SMEM_TOTAL;
    cfg.stream = 0;
    cudaLaunchAttribute attrs[1];
    attrs[0].id = cudaLaunchAttributeProgrammaticStreamSerialization;
    attrs[0].val.programmaticStreamSerializationAllowed = 1;
    cfg.attrs = attrs;
    cfg.numAttrs = 1;
    cudaLaunchKernelEx(&cfg, fused_kernel, W1, b1, W2, b2, W3, b3,
                       out, steps);
}

// round 15
// speedup vs baseline: 1.4117x; 1.1033x over previous
#include <cuda_runtime.h>
#include <cuda_fp16.h>
#include <cstdint>

// ---------------------------------------------------------------------------
// Fused LSTMDiscriminator, round 15: exact R12 loop (proven 21.0us / 7.8e-5)
// with the prep kernel's W_ih fold spread across 16 blocks (was 1 block with
// a 16-deep serial loop -> gated the fused grid-sync). f16x2 tanh (R14)
// reverted: neutral time, 8x worse error.
// ---------------------------------------------------------------------------

#define GATES    512
#define HID      128
#define EMB      64
#define NSEL     512
#define MAXSTEPS 20
#define AG       4
#define PW1      129
#define PW2      65
#define NBLK     (NSEL/AG)   // 128 blocks
#define NTHR     512

// SMEM layout for main kernel (bytes)
#define OFF_XS   0                        // 4096 : h ping-pong [2][128][8] f16
#define OFF_VMT  4096                     // 1280 : float4 (vx,vy,mask,0) [4][20]
#define OFF_SH   5376                     // 2048 : final h fp32 [4][128]
#define OFF_S1   7424                     // 1024
#define OFF_S2   8448                     // 512
#define OFF_W1S  8960                     // 33024: W1 pitch-129
#define OFF_W2S  41984                    // 8320 : W2 pitch-65
#define SMEM_TOTAL 50304

// shared precomputed state (written by prep_kernel each call — deterministic)
__device__ __align__(16) uint4  g_Afrag[16 * 512];        // [j4][tid] frag regs
__device__ __align__(16) float4 g_wc[GATES];              // folded input coefs
__device__ __align__(16) float4 g_vmt[NSEL * MAXSTEPS];   // (vx,vy,mask,0)

__device__ __forceinline__ float tanha(float x) {
    float y;
    asm("tanh.approx.f32 %0, %1;" : "=f"(y) : "f"(x));
    return y;
}
__device__ __forceinline__ float sigf(float x) {
    return fmaf(tanha(0.5f * x), 0.5f, 0.5f);
}

__device__ __forceinline__ void mma_acc(float d[4], const uint32_t* a,
                                        uint32_t b0, uint32_t b1) {
    asm volatile(
        "mma.sync.aligned.m16n8k16.row.col.f32.f16.f16.f32 "
        "{%0,%1,%2,%3},{%4,%5,%6,%7},{%8,%9},{%0,%1,%2,%3};"
        : "+f"(d[0]), "+f"(d[1]), "+f"(d[2]), "+f"(d[3])
        : "r"(a[0]), "r"(a[1]), "r"(a[2]), "r"(a[3]), "r"(b0), "r"(b1));
}

// =============================== prep kernel ================================
// blocks 0..15  : A-fragment packing (8192 uint4)
// blocks 16..31 : W_ih fold, 32 gate rows per block (no serial loop)
// blocks 32..   : velocity/mask gather
__global__ void __launch_bounds__(512) prep_kernel(
    const float* __restrict__ obs, const float* __restrict__ pred,
    const void*  __restrict__ bsplit,
    const float* __restrict__ W_emb, const float* __restrict__ b_emb,
    const float* __restrict__ W_ih,  const float* __restrict__ W_hh,
    const float* __restrict__ b_ih,  const float* __restrict__ b_hh,
    int N, int T_obs, int steps)
{
    // let the dependent fused kernel launch right away (it grid-syncs
    // before consuming our outputs)
    cudaTriggerProgrammaticLaunchCompletion();

    const int b = blockIdx.x, tid = threadIdx.x;

    if (b < 16) {
        // A-fragment packing in exact per-thread register order.
        // tile0 = gates {i(0), g(2)}, tile1 = {f(1), o(3)}; A{tile}[kc] =
        // {gA[k..k+1], gB[k..k+1], gA[k+8..k+9], gB[k+8..k+9]}, k = kc*16+2q
        const int i     = b * 512 + tid;
        const int tid_m = i & 511;
        const int j4    = i >> 9;
        const int u     = 8 * (tid_m >> 5) + ((tid_m >> 2) & 7);
        const int q     = tid_m & 3;
        const int tile  = j4 >> 3;
        const int kc    = j4 & 7;
        const int gA    = tile ? 1 : 0;
        const int gB    = tile ? 3 : 2;
        const int k     = kc * 16 + 2 * q;
        const float* WA = W_hh + (size_t)(gA * 128 + u) * HID;
        const float* WB = W_hh + (size_t)(gB * 128 + u) * HID;
        __half2 hx = __floats2half2_rn(WA[k],     WA[k + 1]);
        __half2 hy = __floats2half2_rn(WB[k],     WB[k + 1]);
        __half2 hz = __floats2half2_rn(WA[k + 8], WA[k + 9]);
        __half2 hw = __floats2half2_rn(WB[k + 8], WB[k + 9]);
        uint4 o;
        o.x = *(const uint32_t*)&hx;
        o.y = *(const uint32_t*)&hy;
        o.z = *(const uint32_t*)&hz;
        o.w = *(const uint32_t*)&hw;
        g_Afrag[j4 * 512 + tid_m] = o;
    } else if (b < 32) {
        // fold W_ih @ W_emb (+bias) — 32 rows per block, one shot
        const int e0  = (tid & 15) << 2;
        const int row = (b - 16) * 32 + (tid >> 4);
        float we0[4], we1[4], be4[4];
        #pragma unroll
        for (int j = 0; j < 4; j++) {
            float2 we = ((const float2*)W_emb)[e0 + j];
            we0[j] = we.x; we1[j] = we.y;
            be4[j] = b_emb[e0 + j];
        }
        float4 v = *(const float4*)(W_ih + (size_t)row * EMB + e0);
        float p0 = v.x*we0[0] + v.y*we0[1] + v.z*we0[2] + v.w*we0[3];
        float p1 = v.x*we1[0] + v.y*we1[1] + v.z*we1[2] + v.w*we1[3];
        float p2 = v.x*be4[0] + v.y*be4[1] + v.z*be4[2] + v.w*be4[3];
        #pragma unroll
        for (int mdist = 8; mdist >= 1; mdist >>= 1) {
            p0 += __shfl_xor_sync(0xffffffffu, p0, mdist);
            p1 += __shfl_xor_sync(0xffffffffu, p1, mdist);
            p2 += __shfl_xor_sync(0xffffffffu, p2, mdist);
        }
        if ((tid & 15) == 0) {
            float bc = p2 + b_ih[row] + b_hh[row];
            g_wc[row] = make_float4(4.0f * p0, 4.0f * p1, bc, 0.f);
        }
    } else {
        // velocity/mask gather for all 512 selected agents
        const int item = (b - 32) * 512 + tid;
        if (item < NSEL * steps) {
            const int row = item / steps;
            const int t   = item - row * steps;
            const int* p32 = (const int*)bsplit;   // dtype-robust int32/int64
            int agent = (p32[NSEL] == N) ? p32[row]
                                         : (int)((const long long*)bsplit)[row];
            const float* f0 = (t < T_obs)
                ? obs  + ((size_t)t * N + agent) * 2
                : pred + ((size_t)(t - T_obs) * N + agent) * 2;
            int t1 = t + 1;
            const float* f1 = (t1 < T_obs)
                ? obs  + ((size_t)t1 * N + agent) * 2
                : pred + ((size_t)(t1 - T_obs) * N + agent) * 2;
            float x0 = f0[0], x1 = f1[0];
            float y0 = f0[1], y1 = f1[1];
            bool m = !(isnan(x0) || isnan(x1));
            g_vmt[row * MAXSTEPS + t] = make_float4(m ? (x1 - x0) : 0.f,
                                                    m ? (y1 - y0) : 0.f,
                                                    m ? 1.f : 0.f, 0.f);
        }
    }
}

// =============================== main kernel ================================
__global__ void __launch_bounds__(NTHR, 1) fused_kernel(
    const float* __restrict__ W1, const float* __restrict__ b1,
    const float* __restrict__ W2, const float* __restrict__ b2,
    const float* __restrict__ W3, const float* __restrict__ b3,
    float* __restrict__ out,
    int steps)
{
    extern __shared__ char smraw[];
    __half*  Xs    = (__half*) (smraw + OFF_XS);   // [2][128][8]
    float4*  s_vmt = (float4*) (smraw + OFF_VMT);  // [agent][t]
    float*   sh    = (float*)  (smraw + OFF_SH);
    float*   s1    = (float*)  (smraw + OFF_S1);
    float*   s2    = (float*)  (smraw + OFF_S2);
    float*   W1s   = (float*)  (smraw + OFF_W1S);
    float*   W2s   = (float*)  (smraw + OFF_W2S);

    const int tid  = threadIdx.x;
    const int w    = tid >> 5;
    const int lane = tid & 31;
    const int r    = lane >> 2;
    const int q    = lane & 3;           // agent owned by this thread
    const int row0 = blockIdx.x * AG;
    const int u    = 8 * w + r;          // hidden unit owned by this thread

    // ===== independent prologue (overlaps prep kernel via PDL) ============
    #pragma unroll
    for (int k = 0; k < 4; k++) {
        int i = tid + 512 * k;
        float4 v = ((const float4*)W1)[i];
        int row = i >> 5;
        int col = (i & 31) << 2;
        float* p = W1s + row * PW1 + col;
        p[0] = v.x; p[1] = v.y; p[2] = v.z; p[3] = v.w;
    }
    {
        int i = tid;
        float4 v = ((const float4*)W2)[i];
        int row = i >> 4;
        int col = (i & 15) << 2;
        float* p = W2s + row * PW2 + col;
        p[0] = v.x; p[1] = v.y; p[2] = v.z; p[3] = v.w;
    }
    ((uint32_t*)Xs)[tid]       = 0u;
    ((uint32_t*)Xs)[tid + 512] = 0u;

    // ===== wait for prep outputs, then dependent prologue ==================
    cudaGridDependencySynchronize();

    // A fragments straight into registers (16 coalesced LDG.128)
    uint4 A0v[8], A1v[8];
    #pragma unroll
    for (int kc = 0; kc < 8; kc++) A0v[kc] = g_Afrag[kc * 512 + tid];
    #pragma unroll
    for (int kc = 0; kc < 8; kc++) A1v[kc] = g_Afrag[(8 + kc) * 512 + tid];

    // folded input coefficients (L2-hot, quad-broadcast)
    float wc0[4], wc1[4], bcr[4];
    #pragma unroll
    for (int g = 0; g < 4; g++) {
        float4 wc = g_wc[g * 128 + u];
        wc0[g] = wc.x; wc1[g] = wc.y; bcr[g] = wc.z;
    }

    // vmt slice for this block's 4 agents (80 float4, coalesced)
    if (tid < AG * MAXSTEPS)
        s_vmt[tid] = g_vmt[row0 * MAXSTEPS + tid];

    __syncthreads();   // the ONE prologue barrier

    float c0 = 0.f, h0 = 0.f;           // single cell: (agent q, unit u)

    const uint32_t xs_base = (uint32_t)__cvta_generic_to_shared(Xs);
    const uint32_t ldm_off = xs_base + lane * 16;
    const uint32_t sts_off = xs_base + u * 16 + q * 4;
    const float4*  vmt_a   = s_vmt + q * MAXSTEPS;

    // =========================== recurrence ===============================
    #pragma unroll 1
    for (int t = 0; t < steps; t++) {
        const int cur = t & 1;

        float4 vm = vmt_a[t];
        const bool m = (vm.z != 0.f);
        float s_i = fmaf(vm.x, wc0[0], fmaf(vm.y, wc1[0], bcr[0]));
        float s_f = fmaf(vm.x, wc0[1], fmaf(vm.y, wc1[1], bcr[1]));
        float s_g = fmaf(vm.x, wc0[2], fmaf(vm.y, wc1[2], bcr[2]));
        float s_o = fmaf(vm.x, wc0[3], fmaf(vm.y, wc1[3], bcr[3]));

        __syncthreads();   // h(t) stores visible

        // load all 4 B chunks upfront
        uint32_t B[4][4];
        const uint32_t xc = ldm_off + cur * 2048;
        #pragma unroll
        for (int cch = 0; cch < 4; cch++) {
            asm volatile(
                "ldmatrix.sync.aligned.m8n8.x4.trans.shared.b16 "
                "{%0,%1,%2,%3}, [%4];"
                : "=r"(B[cch][0]), "=r"(B[cch][1]),
                  "=r"(B[cch][2]), "=r"(B[cch][3])
                : "r"(xc + cch * 512));
        }

        // tile0: gates i (elem 0) and g (elem 2) — finish first
        float d0a[4] = { s_i, 0.f, s_g, 0.f };
        float d0b[4] = { 0.f, 0.f, 0.f, 0.f };
        #pragma unroll
        for (int cch = 0; cch < 4; cch++) {
            mma_acc(d0a, (const uint32_t*)&A0v[2 * cch],     B[cch][0], B[cch][1]);
            mma_acc(d0b, (const uint32_t*)&A0v[2 * cch + 1], B[cch][2], B[cch][3]);
        }
        float iv = sigf (d0a[0] + d0b[0]);
        float gv = tanha(d0a[2] + d0b[2]);

        // tile1: gates f (elem 0) and o (elem 2) — MUFU above overlaps this
        float d1a[4] = { s_f, 0.f, s_o, 0.f };
        float d1b[4] = { 0.f, 0.f, 0.f, 0.f };
        #pragma unroll
        for (int cch = 0; cch < 4; cch++) {
            mma_acc(d1a, (const uint32_t*)&A1v[2 * cch],     B[cch][0], B[cch][1]);
            mma_acc(d1b, (const uint32_t*)&A1v[2 * cch + 1], B[cch][2], B[cch][3]);
        }
        float prod = iv * gv;
        float fv = sigf(d1a[0] + d1b[0]);
        float ov = sigf(d1a[2] + d1b[2]);
        float c2 = fmaf(fv, c0, prod);
        float h2 = ov * tanha(c2);
        if (m) { c0 = c2; h0 = h2; }

        {
            __half hh = __float2half_rn(h0);
            asm volatile("st.shared.b16 [%0], %1;"
                         :: "r"(sts_off + ((cur ^ 1) << 11)),
                            "h"(*(const uint16_t*)&hh));
        }
    }

    // =========================== fused MLP tail ===========================
    sh[q * HID + u] = h0;
    __syncthreads();

    // layer 1: (4 x 128) @ W1^T -> relu
    if (tid < 256) {
        const int u1 = tid & 63;
        const int aa = tid >> 6;
        float acc = b1[u1];
        const float* wr = W1s + u1 * PW1;
        const float* hv = sh + aa * HID;
        #pragma unroll
        for (int k = 0; k < HID; k++) acc = fmaf(wr[k], hv[k], acc);
        s1[aa * 64 + u1] = fmaxf(acc, 0.f);
    }
    __syncthreads();

    // layer 2: (4 x 64) @ W2^T -> relu
    if (tid < 128) {
        const int u2 = tid & 31;
        const int aa = tid >> 5;
        float acc = b2[u2];
        const float* wr = W2s + u2 * PW2;
        const float* xv = s1 + aa * 64;
        #pragma unroll
        for (int k = 0; k < 64; k++) acc = fmaf(wr[k], xv[k], acc);
        s2[aa * 32 + u2] = fmaxf(acc, 0.f);
    }
    __syncthreads();

    // layer 3
    if (tid < AG) {
        float acc = b3[0];
        #pragma unroll
        for (int k = 0; k < 32; k++) acc += W3[k] * s2[tid * 32 + k];
        out[row0 + tid] = fmaxf(acc, 0.f);
    }
}

// ------------------------------- launcher ----------------------------------
extern "C" void kernel_launch(void* const* d_in, const int* in_sizes, int n_in,
                              void* d_out, int out_size) {
    const float* observed   = (const float*)d_in[0];
    const float* prediction = (const float*)d_in[1];
    const void*  bsplit     = d_in[3];
    const float* W_emb      = (const float*)d_in[4];
    const float* b_emb      = (const float*)d_in[5];
    const float* W_ih       = (const float*)d_in[6];
    const float* W_hh       = (const float*)d_in[7];
    const float* b_ih       = (const float*)d_in[8];
    const float* b_hh       = (const float*)d_in[9];
    const float* W1         = (const float*)d_in[10];
    const float* b1         = (const float*)d_in[11];
    const float* W2         = (const float*)d_in[12];
    const float* b2         = (const float*)d_in[13];
    const float* W3         = (const float*)d_in[14];
    const float* b3         = (const float*)d_in[15];
    float* out = (float*)d_out;

    const int N      = in_sizes[2] / 2;               // goals: (N,2)
    const int T_obs  = in_sizes[0] / (2 * N);
    const int T_pred = in_sizes[1] / (2 * N);
    int steps = T_obs + T_pred - 1;
    if (steps > MAXSTEPS) steps = MAXSTEPS;

    // prep grid: 16 (A-frag) + 16 (fold) + ceil(512*steps/512) (vmt)
    const int vmt_blocks = (NSEL * steps + 511) / 512;
    prep_kernel<<<32 + vmt_blocks, 512>>>(
        observed, prediction, bsplit,
        W_emb, b_emb, W_ih, W_hh, b_ih, b_hh,
        N, T_obs, steps);

    cudaFuncSetAttribute(fused_kernel, cudaFuncAttributeMaxDynamicSharedMemorySize,
                         SMEM_TOTAL);

    // PDL: fused launches as soon as prep triggers; it grid-syncs internally
    cudaLaunchConfig_t cfg = {};
    cfg.gridDim  = dim3(NBLK, 1, 1);
    cfg.blockDim = dim3(NTHR, 1, 1);
    cfg.dynamicSmemBytes = SMEM_TOTAL;
    cfg.stream = 0;
    cudaLaunchAttribute attrs[1];
    attrs[0].id = cudaLaunchAttributeProgrammaticStreamSerialization;
    attrs[0].val.programmaticStreamSerializationAllowed = 1;
    cfg.attrs = attrs;
    cfg.numAttrs = 1;
    cudaLaunchKernelEx(&cfg, fused_kernel, W1, b1, W2, b2, W3, b3,
                       out, steps);
}

// round 16
// speedup vs baseline: 1.4140x; 1.0017x over previous
#include <cuda_runtime.h>
#include <cuda_fp16.h>
#include <cstdint>

// ---------------------------------------------------------------------------
// Fused LSTMDiscriminator, round 16: R15 (19.2us) with the velocity/mask
// gather moved OUT of prep INTO the fused kernel's pre-grid-sync prologue
// (it depends only on harness inputs, and PDL gives a free overlap window).
// Prep shrinks to 32 one-shot weight-transform blocks -> earlier grid-sync
// release for all 128 fused blocks.
// ---------------------------------------------------------------------------

#define GATES    512
#define HID      128
#define EMB      64
#define NSEL     512
#define MAXSTEPS 20
#define AG       4
#define PW1      129
#define PW2      65
#define NBLK     (NSEL/AG)   // 128 blocks
#define NTHR     512

// SMEM layout for main kernel (bytes)
#define OFF_XS   0                        // 4096 : h ping-pong [2][128][8] f16
#define OFF_VMT  4096                     // 1280 : float4 (vx,vy,mask,0) [4][20]
#define OFF_SH   5376                     // 2048 : final h fp32 [4][128]
#define OFF_S1   7424                     // 1024
#define OFF_S2   8448                     // 512
#define OFF_W1S  8960                     // 33024: W1 pitch-129
#define OFF_W2S  41984                    // 8320 : W2 pitch-65
#define SMEM_TOTAL 50304

// shared precomputed state (written by prep_kernel each call — deterministic)
__device__ __align__(16) uint4  g_Afrag[16 * 512];        // [j4][tid] frag regs
__device__ __align__(16) float4 g_wc[GATES];              // folded input coefs

__device__ __forceinline__ float tanha(float x) {
    float y;
    asm("tanh.approx.f32 %0, %1;" : "=f"(y) : "f"(x));
    return y;
}
__device__ __forceinline__ float sigf(float x) {
    return fmaf(tanha(0.5f * x), 0.5f, 0.5f);
}

__device__ __forceinline__ void mma_acc(float d[4], const uint32_t* a,
                                        uint32_t b0, uint32_t b1) {
    asm volatile(
        "mma.sync.aligned.m16n8k16.row.col.f32.f16.f16.f32 "
        "{%0,%1,%2,%3},{%4,%5,%6,%7},{%8,%9},{%0,%1,%2,%3};"
        : "+f"(d[0]), "+f"(d[1]), "+f"(d[2]), "+f"(d[3])
        : "r"(a[0]), "r"(a[1]), "r"(a[2]), "r"(a[3]), "r"(b0), "r"(b1));
}

// =============================== prep kernel ================================
// blocks 0..15  : A-fragment packing (8192 uint4)
// blocks 16..31 : W_ih fold, 32 gate rows per block (one shot)
__global__ void __launch_bounds__(512) prep_kernel(
    const float* __restrict__ W_emb, const float* __restrict__ b_emb,
    const float* __restrict__ W_ih,  const float* __restrict__ W_hh,
    const float* __restrict__ b_ih,  const float* __restrict__ b_hh)
{
    cudaTriggerProgrammaticLaunchCompletion();

    const int b = blockIdx.x, tid = threadIdx.x;

    if (b < 16) {
        // A-fragment packing in exact per-thread register order.
        // tile0 = gates {i(0), g(2)}, tile1 = {f(1), o(3)}; A{tile}[kc] =
        // {gA[k..k+1], gB[k..k+1], gA[k+8..k+9], gB[k+8..k+9]}, k = kc*16+2q
        const int i     = b * 512 + tid;
        const int tid_m = i & 511;
        const int j4    = i >> 9;
        const int u     = 8 * (tid_m >> 5) + ((tid_m >> 2) & 7);
        const int q     = tid_m & 3;
        const int tile  = j4 >> 3;
        const int kc    = j4 & 7;
        const int gA    = tile ? 1 : 0;
        const int gB    = tile ? 3 : 2;
        const int k     = kc * 16 + 2 * q;
        const float* WA = W_hh + (size_t)(gA * 128 + u) * HID;
        const float* WB = W_hh + (size_t)(gB * 128 + u) * HID;
        __half2 hx = __floats2half2_rn(WA[k],     WA[k + 1]);
        __half2 hy = __floats2half2_rn(WB[k],     WB[k + 1]);
        __half2 hz = __floats2half2_rn(WA[k + 8], WA[k + 9]);
        __half2 hw = __floats2half2_rn(WB[k + 8], WB[k + 9]);
        uint4 o;
        o.x = *(const uint32_t*)&hx;
        o.y = *(const uint32_t*)&hy;
        o.z = *(const uint32_t*)&hz;
        o.w = *(const uint32_t*)&hw;
        g_Afrag[j4 * 512 + tid_m] = o;
    } else {
        // fold W_ih @ W_emb (+bias) — 32 rows per block, one shot
        const int e0  = (tid & 15) << 2;
        const int row = (b - 16) * 32 + (tid >> 4);
        float we0[4], we1[4], be4[4];
        #pragma unroll
        for (int j = 0; j < 4; j++) {
            float2 we = ((const float2*)W_emb)[e0 + j];
            we0[j] = we.x; we1[j] = we.y;
            be4[j] = b_emb[e0 + j];
        }
        float4 v = *(const float4*)(W_ih + (size_t)row * EMB + e0);
        float p0 = v.x*we0[0] + v.y*we0[1] + v.z*we0[2] + v.w*we0[3];
        float p1 = v.x*we1[0] + v.y*we1[1] + v.z*we1[2] + v.w*we1[3];
        float p2 = v.x*be4[0] + v.y*be4[1] + v.z*be4[2] + v.w*be4[3];
        #pragma unroll
        for (int mdist = 8; mdist >= 1; mdist >>= 1) {
            p0 += __shfl_xor_sync(0xffffffffu, p0, mdist);
            p1 += __shfl_xor_sync(0xffffffffu, p1, mdist);
            p2 += __shfl_xor_sync(0xffffffffu, p2, mdist);
        }
        if ((tid & 15) == 0) {
            float bc = p2 + b_ih[row] + b_hh[row];
            g_wc[row] = make_float4(4.0f * p0, 4.0f * p1, bc, 0.f);
        }
    }
}

// =============================== main kernel ================================
__global__ void __launch_bounds__(NTHR, 1) fused_kernel(
    const float* __restrict__ obs, const float* __restrict__ pred,
    const void*  __restrict__ bsplit,
    const float* __restrict__ W1, const float* __restrict__ b1,
    const float* __restrict__ W2, const float* __restrict__ b2,
    const float* __restrict__ W3, const float* __restrict__ b3,
    float* __restrict__ out,
    int N, int T_obs, int steps)
{
    extern __shared__ char smraw[];
    __half*  Xs    = (__half*) (smraw + OFF_XS);   // [2][128][8]
    float4*  s_vmt = (float4*) (smraw + OFF_VMT);  // [agent][t]
    float*   sh    = (float*)  (smraw + OFF_SH);
    float*   s1    = (float*)  (smraw + OFF_S1);
    float*   s2    = (float*)  (smraw + OFF_S2);
    float*   W1s   = (float*)  (smraw + OFF_W1S);
    float*   W2s   = (float*)  (smraw + OFF_W2S);

    const int tid  = threadIdx.x;
    const int w    = tid >> 5;
    const int lane = tid & 31;
    const int r    = lane >> 2;
    const int q    = lane & 3;           // agent owned by this thread
    const int row0 = blockIdx.x * AG;
    const int u    = 8 * w + r;          // hidden unit owned by this thread

    // ===== independent prologue (overlaps prep kernel via PDL) ============
    // (a) velocity/mask gather for this block's 4 agents — depends only on
    //     harness inputs, so it runs fully inside the PDL overlap window.
    if (tid < AG * steps) {
        const int a = tid / steps;
        const int t = tid - a * steps;
        const int row = row0 + a;
        const int* p32 = (const int*)bsplit;       // dtype-robust int32/int64
        int agent = (p32[NSEL] == N) ? p32[row]
                                     : (int)((const long long*)bsplit)[row];
        const float* f0 = (t < T_obs)
            ? obs  + ((size_t)t * N + agent) * 2
            : pred + ((size_t)(t - T_obs) * N + agent) * 2;
        int t1 = t + 1;
        const float* f1 = (t1 < T_obs)
            ? obs  + ((size_t)t1 * N + agent) * 2
            : pred + ((size_t)(t1 - T_obs) * N + agent) * 2;
        float x0 = f0[0], x1 = f1[0];
        float y0 = f0[1], y1 = f1[1];
        bool m = !(isnan(x0) || isnan(x1));
        s_vmt[a * MAXSTEPS + t] = make_float4(m ? (x1 - x0) : 0.f,
                                              m ? (y1 - y0) : 0.f,
                                              m ? 1.f : 0.f, 0.f);
    }

    // (b) W1 / W2 pitched staging for the MLP tail
    #pragma unroll
    for (int k = 0; k < 4; k++) {
        int i = tid + 512 * k;
        float4 v = ((const float4*)W1)[i];
        int row = i >> 5;
        int col = (i & 31) << 2;
        float* p = W1s + row * PW1 + col;
        p[0] = v.x; p[1] = v.y; p[2] = v.z; p[3] = v.w;
    }
    {
        int i = tid;
        float4 v = ((const float4*)W2)[i];
        int row = i >> 4;
        int col = (i & 15) << 2;
        float* p = W2s + row * PW2 + col;
        p[0] = v.x; p[1] = v.y; p[2] = v.z; p[3] = v.w;
    }
    // (c) zero both h ping-pong buffers
    ((uint32_t*)Xs)[tid]       = 0u;
    ((uint32_t*)Xs)[tid + 512] = 0u;

    // ===== wait for prep outputs (weight transforms only) ==================
    cudaGridDependencySynchronize();

    // A fragments straight into registers (16 coalesced LDG.128)
    uint4 A0v[8], A1v[8];
    #pragma unroll
    for (int kc = 0; kc < 8; kc++) A0v[kc] = g_Afrag[kc * 512 + tid];
    #pragma unroll
    for (int kc = 0; kc < 8; kc++) A1v[kc] = g_Afrag[(8 + kc) * 512 + tid];

    // folded input coefficients (L2-hot, quad-broadcast)
    float wc0[4], wc1[4], bcr[4];
    #pragma unroll
    for (int g = 0; g < 4; g++) {
        float4 wc = g_wc[g * 128 + u];
        wc0[g] = wc.x; wc1[g] = wc.y; bcr[g] = wc.z;
    }

    __syncthreads();   // the ONE prologue barrier (vmt/Xs/W staging visible)

    float c0 = 0.f, h0 = 0.f;           // single cell: (agent q, unit u)

    const uint32_t xs_base = (uint32_t)__cvta_generic_to_shared(Xs);
    const uint32_t ldm_off = xs_base + lane * 16;
    const uint32_t sts_off = xs_base + u * 16 + q * 4;
    const float4*  vmt_a   = s_vmt + q * MAXSTEPS;

    // =========================== recurrence ===============================
    #pragma unroll 1
    for (int t = 0; t < steps; t++) {
        const int cur = t & 1;

        float4 vm = vmt_a[t];
        const bool m = (vm.z != 0.f);
        float s_i = fmaf(vm.x, wc0[0], fmaf(vm.y, wc1[0], bcr[0]));
        float s_f = fmaf(vm.x, wc0[1], fmaf(vm.y, wc1[1], bcr[1]));
        float s_g = fmaf(vm.x, wc0[2], fmaf(vm.y, wc1[2], bcr[2]));
        float s_o = fmaf(vm.x, wc0[3], fmaf(vm.y, wc1[3], bcr[3]));

        __syncthreads();   // h(t) stores visible

        // load all 4 B chunks upfront
        uint32_t B[4][4];
        const uint32_t xc = ldm_off + cur * 2048;
        #pragma unroll
        for (int cch = 0; cch < 4; cch++) {
            asm volatile(
                "ldmatrix.sync.aligned.m8n8.x4.trans.shared.b16 "
                "{%0,%1,%2,%3}, [%4];"
                : "=r"(B[cch][0]), "=r"(B[cch][1]),
                  "=r"(B[cch][2]), "=r"(B[cch][3])
                : "r"(xc + cch * 512));
        }

        // tile0: gates i (elem 0) and g (elem 2) — finish first
        float d0a[4] = { s_i, 0.f, s_g, 0.f };
        float d0b[4] = { 0.f, 0.f, 0.f, 0.f };
        #pragma unroll
        for (int cch = 0; cch < 4; cch++) {
            mma_acc(d0a, (const uint32_t*)&A0v[2 * cch],     B[cch][0], B[cch][1]);
            mma_acc(d0b, (const uint32_t*)&A0v[2 * cch + 1], B[cch][2], B[cch][3]);
        }
        float iv = sigf (d0a[0] + d0b[0]);
        float gv = tanha(d0a[2] + d0b[2]);

        // tile1: gates f (elem 0) and o (elem 2) — MUFU above overlaps this
        float d1a[4] = { s_f, 0.f, s_o, 0.f };
        float d1b[4] = { 0.f, 0.f, 0.f, 0.f };
        #pragma unroll
        for (int cch = 0; cch < 4; cch++) {
            mma_acc(d1a, (const uint32_t*)&A1v[2 * cch],     B[cch][0], B[cch][1]);
            mma_acc(d1b, (const uint32_t*)&A1v[2 * cch + 1], B[cch][2], B[cch][3]);
        }
        float prod = iv * gv;
        float fv = sigf(d1a[0] + d1b[0]);
        float ov = sigf(d1a[2] + d1b[2]);
        float c2 = fmaf(fv, c0, prod);
        float h2 = ov * tanha(c2);
        if (m) { c0 = c2; h0 = h2; }

        {
            __half hh = __float2half_rn(h0);
            asm volatile("st.shared.b16 [%0], %1;"
                         :: "r"(sts_off + ((cur ^ 1) << 11)),
                            "h"(*(const uint16_t*)&hh));
        }
    }

    // =========================== fused MLP tail ===========================
    sh[q * HID + u] = h0;
    __syncthreads();

    // layer 1: (4 x 128) @ W1^T -> relu
    if (tid < 256) {
        const int u1 = tid & 63;
        const int aa = tid >> 6;
        float acc = b1[u1];
        const float* wr = W1s + u1 * PW1;
        const float* hv = sh + aa * HID;
        #pragma unroll
        for (int k = 0; k < HID; k++) acc = fmaf(wr[k], hv[k], acc);
        s1[aa * 64 + u1] = fmaxf(acc, 0.f);
    }
    __syncthreads();

    // layer 2: (4 x 64) @ W2^T -> relu
    if (tid < 128) {
        const int u2 = tid & 31;
        const int aa = tid >> 5;
        float acc = b2[u2];
        const float* wr = W2s + u2 * PW2;
        const float* xv = s1 + aa * 64;
        #pragma unroll
        for (int k = 0; k < 64; k++) acc = fmaf(wr[k], xv[k], acc);
        s2[aa * 32 + u2] = fmaxf(acc, 0.f);
    }
    __syncthreads();

    // layer 3
    if (tid < AG) {
        float acc = b3[0];
        #pragma unroll
        for (int k = 0; k < 32; k++) acc += W3[k] * s2[tid * 32 + k];
        out[row0 + tid] = fmaxf(acc, 0.f);
    }
}

// ------------------------------- launcher ----------------------------------
extern "C" void kernel_launch(void* const* d_in, const int* in_sizes, int n_in,
                              void* d_out, int out_size) {
    const float* observed   = (const float*)d_in[0];
    const float* prediction = (const float*)d_in[1];
    const void*  bsplit     = d_in[3];
    const float* W_emb      = (const float*)d_in[4];
    const float* b_emb      = (const float*)d_in[5];
    const float* W_ih       = (const float*)d_in[6];
    const float* W_hh       = (const float*)d_in[7];
    const float* b_ih       = (const float*)d_in[8];
    const float* b_hh       = (const float*)d_in[9];
    const float* W1         = (const float*)d_in[10];
    const float* b1         = (const float*)d_in[11];
    const float* W2         = (const float*)d_in[12];
    const float* b2         = (const float*)d_in[13];
    const float* W3         = (const float*)d_in[14];
    const float* b3         = (const float*)d_in[15];
    float* out = (float*)d_out;

    const int N      = in_sizes[2] / 2;               // goals: (N,2)
    const int T_obs  = in_sizes[0] / (2 * N);
    const int T_pred = in_sizes[1] / (2 * N);
    int steps = T_obs + T_pred - 1;
    if (steps > MAXSTEPS) steps = MAXSTEPS;

    // prep grid: 16 (A-frag) + 16 (fold) — weight transforms only
    prep_kernel<<<32, 512>>>(W_emb, b_emb, W_ih, W_hh, b_ih, b_hh);

    cudaFuncSetAttribute(fused_kernel, cudaFuncAttributeMaxDynamicSharedMemorySize,
                         SMEM_TOTAL);

    // PDL: fused launches as soon as prep triggers; it grid-syncs internally
    cudaLaunchConfig_t cfg = {};
    cfg.gridDim  = dim3(NBLK, 1, 1);
    cfg.blockDim = dim3(NTHR, 1, 1);
    cfg.dynamicSmemBytes = SMEM_TOTAL;
    cfg.stream = 0;
    cudaLaunchAttribute attrs[1];
    attrs[0].id = cudaLaunchAttributeProgrammaticStreamSerialization;
    attrs[0].val.programmaticStreamSerializationAllowed = 1;
    cfg.attrs = attrs;
    cfg.numAttrs = 1;
    cudaLaunchKernelEx(&cfg, fused_kernel,
                       observed, prediction, bsplit,
                       W1, b1, W2, b2, W3, b3,
                       out, N, T_obs, steps);
}